// round 17
// baseline (speedup 1.0000x reference)
#include <cuda_runtime.h>
#include <cuda_fp16.h>
#include <cstdint>

// ---------------- scratch (no cudaMalloc allowed) ----------------
#define ELEMS 33554432           // B*N*L*512
#define IN_ELEMS 8388608         // B*N*L*128
__device__ __half g_qh[ELEMS];                 // Q fp16 row-major [token][512]
__device__ __half g_kh[ELEMS];                 // K fp16 row-major
__device__ __half g_vh[ELEMS];                 // V fp16 row-major
__device__ __half g_vt[ELEMS];                 // V fp16 transposed [bn][h][d][key]
__device__ __half g_ao[ELEMS];                 // attention out fp16
__device__ __half g_inq[IN_ELEMS];             // fp16 inputs
__device__ __half g_ink[IN_ELEMS];
__device__ __half g_inv[IN_ELEMS];
__device__ __half g_wqt[65536];                // W^T [n=512][k=128] fp16
__device__ __half g_wkt[65536];
__device__ __half g_wvt[65536];
__device__ __half g_wot[262144];               // Wo^T [n=512][k=512] fp16

// ---------------- helpers ----------------
__device__ __forceinline__ void mma16(float* d, const uint32_t* a, const uint32_t* b) {
    asm volatile(
        "mma.sync.aligned.m16n8k16.row.col.f32.f16.f16.f32 "
        "{%0,%1,%2,%3}, {%4,%5,%6,%7}, {%8,%9}, {%0,%1,%2,%3};"
        : "+f"(d[0]), "+f"(d[1]), "+f"(d[2]), "+f"(d[3])
        : "r"(a[0]), "r"(a[1]), "r"(a[2]), "r"(a[3]), "r"(b[0]), "r"(b[1]));
}

__device__ __forceinline__ uint32_t smem_u32(const void* p) {
    return (uint32_t)__cvta_generic_to_shared(p);
}
__device__ __forceinline__ void cp16(uint32_t dst, const void* src) {
    asm volatile("cp.async.cg.shared.global [%0], [%1], 16;" :: "r"(dst), "l"(src));
}
__device__ __forceinline__ void cp_commit() {
    asm volatile("cp.async.commit_group;");
}
template <int N>
__device__ __forceinline__ void cp_wait() {
    asm volatile("cp.async.wait_group %0;" :: "n"(N));
}
__device__ __forceinline__ uint32_t h2u(float lo, float hi) {
    __half2 h = __floats2half2_rn(lo, hi);
    return *(uint32_t*)&h;
}

// ---------------- prep kernels ----------------
__global__ void prep_inputs_kernel(
    const float* __restrict__ q, const float* __restrict__ k,
    const float* __restrict__ v)
{
    int i4 = (blockIdx.x * 256 + threadIdx.x) * 4;
    float4 a = *(const float4*)&q[i4];
    float4 b = *(const float4*)&k[i4];
    float4 c = *(const float4*)&v[i4];
    __half2 h[2];
    h[0] = __floats2half2_rn(a.x, a.y); h[1] = __floats2half2_rn(a.z, a.w);
    *(uint2*)&g_inq[i4] = *(uint2*)h;
    h[0] = __floats2half2_rn(b.x, b.y); h[1] = __floats2half2_rn(b.z, b.w);
    *(uint2*)&g_ink[i4] = *(uint2*)h;
    h[0] = __floats2half2_rn(c.x, c.y); h[1] = __floats2half2_rn(c.z, c.w);
    *(uint2*)&g_inv[i4] = *(uint2*)h;
}

__global__ void prep_wqkv_kernel(
    const float* __restrict__ Wq, const float* __restrict__ Wk,
    const float* __restrict__ Wv)
{
    __shared__ float tile[32][33];
    const float* W = (blockIdx.z == 0) ? Wq : (blockIdx.z == 1) ? Wk : Wv;
    __half* Wt = (blockIdx.z == 0) ? g_wqt : (blockIdx.z == 1) ? g_wkt : g_wvt;
    int kt = blockIdx.y * 32, nt = blockIdx.x * 32;
    int tx = threadIdx.x, ty = threadIdx.y;
    tile[ty][tx] = W[(size_t)(kt + ty) * 512 + nt + tx];
    __syncthreads();
    Wt[(nt + ty) * 128 + kt + tx] = __float2half_rn(tile[tx][ty]);
}

__global__ void prep_wo_kernel(const float* __restrict__ Wo)
{
    __shared__ float tile[32][33];
    int kt = blockIdx.y * 32, nt = blockIdx.x * 32;
    int tx = threadIdx.x, ty = threadIdx.y;
    tile[ty][tx] = Wo[(size_t)(kt + ty) * 512 + nt + tx];
    __syncthreads();
    g_wot[(nt + ty) * 512 + kt + tx] = __float2half_rn(tile[tx][ty]);
}

// ---------------- V transpose: g_vh [token][512] -> g_vt [bn][h][d][key] ----
// One CTA per (bn, h): tile [256 keys][64 d] staged in smem (stride 72).
__global__ __launch_bounds__(256) void transpose_v_kernel()
{
    __shared__ __half sm[256 * 72];
    int h  = blockIdx.x;             // 0..7
    int bn = blockIdx.y;             // 0..255
    int tid = threadIdx.x;

    size_t src = (size_t)bn * 131072 + (size_t)h * 64;     // g_vh rows
    size_t dst = (size_t)bn * 131072 + (size_t)h * 16384;  // g_vt [d][256]

    // read: 256 rows x 64 halves = 2048 uint4 chunks, coalesced
    #pragma unroll
    for (int i = 0; i < 8; i++) {
        int f = tid + i * 256;
        int r = f >> 3, c8 = (f & 7) * 8;
        *(uint4*)&sm[r * 72 + c8] =
            *(const uint4*)&g_vh[src + (size_t)r * 512 + c8];
    }
    __syncthreads();

    // write: 64 d-rows x 256 keys = 2048 uint4 chunks, coalesced on g_vt
    #pragma unroll
    for (int i = 0; i < 8; i++) {
        int f = tid + i * 256;
        int d = f >> 5, k8 = (f & 31) * 8;
        __half tmp[8];
        #pragma unroll
        for (int j = 0; j < 8; j++)
            tmp[j] = sm[(k8 + j) * 72 + d];
        *(uint4*)&g_vt[dst + (size_t)d * 256 + k8] = *(uint4*)tmp;
    }
}

// ================= fp16 GEMM: C = A[M,K] @ Wt[N,K]^T + bias =================
// OUTMODE: 0 = fp32 row-major (final out), 1 = fp16 row-major
#define HS_STRIDE 72
#define HSTAGE_B (2 * 128 * HS_STRIDE * 2)
#define HGEMM_SMEM (3 * HSTAGE_B)               // 110592 B

template <int OUTMODE>
__device__ __forceinline__ void hgemm_body(
    const __half* __restrict__ A, const __half* __restrict__ Wt,
    const float* __restrict__ bias, void* __restrict__ Cout,
    int N, int K)
{
    extern __shared__ char hsm[];

    int tid  = threadIdx.x;
    int lane = tid & 31, warp = tid >> 5;
    int g = lane >> 2, t = lane & 3;
    int wm = (warp & 1) * 64;
    int wn = (warp >> 1) * 64;
    int m0 = blockIdx.y * 128;
    int n0 = blockIdx.x * 128;

    int tr[16], tc[16], tt[16];
    #pragma unroll
    for (int i = 0; i < 16; i++) {
        int ci = tid + i * 128;
        tt[i] = ci >> 10;
        int w = ci & 1023;
        tr[i] = w >> 3; tc[i] = w & 7;
    }

    int nTiles = K / 64;

    auto issue = [&](int tile) {
        if (tile < nTiles) {
            uint32_t stb = smem_u32(hsm) + (tile % 3) * HSTAGE_B;
            int kc = tile * 64;
            #pragma unroll
            for (int i = 0; i < 16; i++) {
                uint32_t dst = stb + (uint32_t)tt[i] * (128 * HS_STRIDE * 2)
                             + (uint32_t)(tr[i] * (HS_STRIDE * 2) + tc[i] * 16);
                const __half* src = tt[i] == 0
                    ? &A[(size_t)(m0 + tr[i]) * K + kc + tc[i] * 8]
                    : &Wt[(size_t)(n0 + tr[i]) * K + kc + tc[i] * 8];
                cp16(dst, src);
            }
        }
        cp_commit();
    };

    float acc[4][8][4] = {};

    issue(0);
    issue(1);

    for (int i = 0; i < nTiles; i++) {
        cp_wait<1>();
        __syncthreads();

        const char* As = hsm + (i % 3) * HSTAGE_B;
        const char* Bs = As + 128 * HS_STRIDE * 2;

        #pragma unroll
        for (int ks = 0; ks < 4; ks++) {
            int kb = ks * 32 + 4 * t;
            uint32_t a[4][4], b[8][2];
            #pragma unroll
            for (int mt = 0; mt < 4; mt++) {
                int r = wm + 16 * mt + g;
                const char* row0 = As + r * (HS_STRIDE * 2);
                const char* row8 = As + (r + 8) * (HS_STRIDE * 2);
                a[mt][0] = *(const uint32_t*)(row0 + kb);
                a[mt][1] = *(const uint32_t*)(row8 + kb);
                a[mt][2] = *(const uint32_t*)(row0 + kb + 16);
                a[mt][3] = *(const uint32_t*)(row8 + kb + 16);
            }
            #pragma unroll
            for (int nt = 0; nt < 8; nt++) {
                const char* rw = Bs + (wn + 8 * nt + g) * (HS_STRIDE * 2);
                b[nt][0] = *(const uint32_t*)(rw + kb);
                b[nt][1] = *(const uint32_t*)(rw + kb + 16);
            }
            #pragma unroll
            for (int mt = 0; mt < 4; mt++)
                #pragma unroll
                for (int nt = 0; nt < 8; nt++)
                    mma16(acc[mt][nt], a[mt], b[nt]);
        }

        issue(i + 2);
    }

    #pragma unroll
    for (int mt = 0; mt < 4; mt++) {
        int r0 = m0 + wm + 16 * mt + g;
        #pragma unroll
        for (int nt = 0; nt < 8; nt++) {
            int col = n0 + wn + 8 * nt + 2 * t;
            float b0 = bias[col], b1 = bias[col + 1];
            float x0 = acc[mt][nt][0] + b0, x1 = acc[mt][nt][1] + b1;
            float x2 = acc[mt][nt][2] + b0, x3 = acc[mt][nt][3] + b1;
            if (OUTMODE == 0) {
                float* C = (float*)Cout;
                *(float2*)&C[(size_t)r0 * N + col] = {x0, x1};
                *(float2*)&C[(size_t)(r0 + 8) * N + col] = {x2, x3};
            } else {
                __half* C = (__half*)Cout;
                uint32_t p0 = h2u(x0, x1), p1 = h2u(x2, x3);
                *(uint32_t*)&C[(size_t)r0 * N + col] = p0;
                *(uint32_t*)&C[(size_t)(r0 + 8) * N + col] = p1;
            }
        }
    }
}

__global__ __launch_bounds__(128, 2) void qkv_proj_kernel(
    const float* __restrict__ bq, const float* __restrict__ bk,
    const float* __restrict__ bv)
{
    if (blockIdx.z == 0)
        hgemm_body<1>(g_inq, g_wqt, bq, g_qh, 512, 128);
    else if (blockIdx.z == 1)
        hgemm_body<1>(g_ink, g_wkt, bk, g_kh, 512, 128);
    else
        hgemm_body<1>(g_inv, g_wvt, bv, g_vh, 512, 128);
}

__global__ __launch_bounds__(128, 2) void out_proj_kernel(
    const float* __restrict__ bo, float* __restrict__ out)
{
    hgemm_body<0>(g_ao, g_wot, bo, out, 512, 512);
}

// ================= attention: all-fp16 mma, no P staging ====================
#define AK_STRIDE 72
#define AK_STAGE (64 * AK_STRIDE)

__global__ __launch_bounds__(256, 2) void attn_kernel()
{
    __shared__ __half Ksm[2][AK_STAGE];
    __shared__ __half Vsm[2][AK_STAGE];

    int tid = threadIdx.x, lane = tid & 31, warp = tid >> 5;
    int g = lane >> 2, t = lane & 3;

    int h  = blockIdx.x;
    int bn = blockIdx.y;
    int half_ = blockIdx.z;
    size_t baseK  = (size_t)bn * 131072 + (size_t)h * 64;
    size_t baseVt = (size_t)bn * 131072 + (size_t)h * 16384;
    size_t baseQ  = baseK + (size_t)half_ * 65536;

    int slr[4], slc[4], slt[4];
    #pragma unroll
    for (int i = 0; i < 4; i++) {
        int ci = tid + i * 256;
        slt[i] = ci >> 9;
        int w = ci & 511;
        slr[i] = w >> 3; slc[i] = w & 7;
    }

    auto issue = [&](int chunk) {
        if (chunk < 4) {
            int kb = chunk * 64;
            #pragma unroll
            for (int i = 0; i < 4; i++) {
                if (slt[i] == 0) {
                    cp16(smem_u32(&Ksm[chunk & 1][slr[i] * AK_STRIDE + slc[i] * 8]),
                         &g_kh[baseK + (size_t)(kb + slr[i]) * 512 + slc[i] * 8]);
                } else {
                    cp16(smem_u32(&Vsm[chunk & 1][slr[i] * AK_STRIDE + slc[i] * 8]),
                         &g_vt[baseVt + (size_t)slr[i] * 256 + kb + slc[i] * 8]);
                }
            }
        }
        cp_commit();
    };

    issue(0);
    issue(1);

    int qr0 = warp * 16;
    const __half2 sc = __float2half2_rn(0.125f);
    uint32_t qa[4][4];
    #pragma unroll
    for (int ks = 0; ks < 4; ks++) {
        size_t r0 = baseQ + (size_t)(qr0 + g) * 512 + 16 * ks + 2 * t;
        size_t r8 = r0 + 8 * 512;
        __half2 v0 = __hmul2(*(const __half2*)&g_qh[r0], sc);
        __half2 v1 = __hmul2(*(const __half2*)&g_qh[r8], sc);
        __half2 v2 = __hmul2(*(const __half2*)&g_qh[r0 + 8], sc);
        __half2 v3 = __hmul2(*(const __half2*)&g_qh[r8 + 8], sc);
        qa[ks][0] = *(uint32_t*)&v0;
        qa[ks][1] = *(uint32_t*)&v1;
        qa[ks][2] = *(uint32_t*)&v2;
        qa[ks][3] = *(uint32_t*)&v3;
    }

    float o[8][4] = {};
    float den0 = 0.0f, den1 = 0.0f;

    #pragma unroll 1
    for (int c = 0; c < 4; c++) {
        cp_wait<1>();
        __syncthreads();
        const __half* Ks = Ksm[c & 1];
        const __half* Vs = Vsm[c & 1];

        float s[8][4] = {};
        #pragma unroll
        for (int ks = 0; ks < 4; ks++) {
            int kb = ks * 16 + 2 * t;
            uint32_t b[8][2];
            #pragma unroll
            for (int nt = 0; nt < 8; nt++) {
                const __half* rw = Ks + (8 * nt + g) * AK_STRIDE + kb;
                b[nt][0] = *(const uint32_t*)rw;
                b[nt][1] = *(const uint32_t*)(rw + 8);
            }
            #pragma unroll
            for (int nt = 0; nt < 8; nt++)
                mma16(s[nt], qa[ks], b[nt]);
        }

        uint32_t p[8][2];
        #pragma unroll
        for (int nt = 0; nt < 8; nt++) {
            float e0 = __expf(s[nt][0]);
            float e1 = __expf(s[nt][1]);
            float e2 = __expf(s[nt][2]);
            float e3 = __expf(s[nt][3]);
            den0 += e0 + e1;
            den1 += e2 + e3;
            p[nt][0] = h2u(e0, e1);
            p[nt][1] = h2u(e2, e3);
        }

        #pragma unroll
        for (int ks = 0; ks < 4; ks++) {
            uint32_t a[4] = {p[2 * ks][0], p[2 * ks][1],
                             p[2 * ks + 1][0], p[2 * ks + 1][1]};
            int kb = ks * 16 + 2 * t;
            uint32_t b[8][2];
            #pragma unroll
            for (int nt = 0; nt < 8; nt++) {
                const __half* rw = Vs + (8 * nt + g) * AK_STRIDE + kb;
                b[nt][0] = *(const uint32_t*)rw;
                b[nt][1] = *(const uint32_t*)(rw + 8);
            }
            #pragma unroll
            for (int nt = 0; nt < 8; nt++)
                mma16(o[nt], a, b[nt]);
        }

        __syncthreads();
        issue(c + 2);
    }

    den0 += __shfl_xor_sync(0xffffffffu, den0, 1);
    den0 += __shfl_xor_sync(0xffffffffu, den0, 2);
    den1 += __shfl_xor_sync(0xffffffffu, den1, 1);
    den1 += __shfl_xor_sync(0xffffffffu, den1, 2);
    float inv0 = 1.0f / den0, inv1 = 1.0f / den1;

    int rg = qr0 + g;
    #pragma unroll
    for (int nt = 0; nt < 8; nt++) {
        int col = 8 * nt + 2 * t;
        uint32_t h0 = h2u(o[nt][0] * inv0, o[nt][1] * inv0);
        uint32_t h1 = h2u(o[nt][2] * inv1, o[nt][3] * inv1);
        *(uint32_t*)&g_ao[baseQ + (size_t)rg * 512 + col] = h0;
        *(uint32_t*)&g_ao[baseQ + (size_t)(rg + 8) * 512 + col] = h1;
    }
}

extern "C" void kernel_launch(void* const* d_in, const int* in_sizes, int n_in,
                              void* d_out, int out_size)
{
    const float* query = (const float*)d_in[0];
    const float* key   = (const float*)d_in[1];
    const float* value = (const float*)d_in[2];
    const float* Wq    = (const float*)d_in[3];
    const float* bq    = (const float*)d_in[4];
    const float* Wk    = (const float*)d_in[5];
    const float* bk    = (const float*)d_in[6];
    const float* Wv    = (const float*)d_in[7];
    const float* bv    = (const float*)d_in[8];
    const float* Wo    = (const float*)d_in[9];
    const float* bo    = (const float*)d_in[10];
    float* out = (float*)d_out;

    prep_inputs_kernel<<<IN_ELEMS / 1024, 256>>>(query, key, value);
    dim3 tb(32, 32);
    prep_wqkv_kernel<<<dim3(16, 4, 3), tb>>>(Wq, Wk, Wv);
    prep_wo_kernel<<<dim3(16, 16), tb>>>(Wo);

    cudaFuncSetAttribute(qkv_proj_kernel,
                         cudaFuncAttributeMaxDynamicSharedMemorySize, HGEMM_SMEM);
    cudaFuncSetAttribute(out_proj_kernel,
                         cudaFuncAttributeMaxDynamicSharedMemorySize, HGEMM_SMEM);

    dim3 gproj(512 / 128, 65536 / 128, 3);
    qkv_proj_kernel<<<gproj, 128, HGEMM_SMEM>>>(bq, bk, bv);

    dim3 gtr(8, 256);
    transpose_v_kernel<<<gtr, 256>>>();

    dim3 gattn(8, 256, 2);
    attn_kernel<<<gattn, 256>>>();

    dim3 gout(512 / 128, 65536 / 128);
    out_proj_kernel<<<gout, 128, HGEMM_SMEM>>>(bo, out);
}